// round 8
// baseline (speedup 1.0000x reference)
#include <cuda_runtime.h>
#include <cstdint>

#define D 128
#define TQ 128
#define TK 64
#define NTHREADS 256
#define NGLOBAL 100
#define LPRE 2048
#define CHUNK 4         // tiles per work unit (uniform units -> balanced waves)
#define SPMAX 9         // max splits per q-tile = ceil(36/CHUNK)
#define BMAX 2
#define SMAX 8192

#define QS_STRIDE 136   // ≡8 mod 32: conflict-free v2 fragment LDS
#define KR_STRIDE 132   // raw rows padded 128->132 (16B-aligned rows, bank-spread)

#define QS_OFF 0
#define K0_OFF (TQ * QS_STRIDE)            // 17408
#define K1_OFF (K0_OFF + TK * KR_STRIDE)   // 25856
#define V0_OFF (K1_OFF + TK * KR_STRIDE)   // 34304
#define V1_OFF (V0_OFF + TK * KR_STRIDE)   // 42752
#define SMEM_FLOATS (V1_OFF + TK * KR_STRIDE)   // 51200 floats = 204.8 KB

typedef unsigned int u32;

// split-K scratch (static device globals: allocation-free)
__device__ float g_Op[(size_t)SPMAX * BMAX * SMAX * D];   // unnormalized partial O
__device__ float g_Ml[SPMAX * BMAX * SMAX];               // per-row running max (log2)
__device__ float g_Ll[SPMAX * BMAX * SMAX];               // per-row partial denom

// visited-tile count for q-tile qt (same formula host+device)
__host__ __device__ __forceinline__ int nt_of(int qt) {
    int nTile = 2 * (qt + 1);            // (qt*TQ + TQ)/TK
    int tLoc = 2;
    int dd = qt * TQ - (LPRE - 1) - TK;  // tile t skipped iff t>=2 && 64t <= dd
    if (dd >= 0) { int t = dd / TK + 1; if (t > 2) tLoc = t; }
    return 2 + (nTile - tLoc);
}

__device__ __forceinline__ u32 to_tf32(float x) {
    u32 r;
    asm("cvt.rna.tf32.f32 %0, %1;" : "=r"(r) : "f"(x));
    return r;
}

__device__ __forceinline__ void mma_tf32(float c[4], u32 a0, u32 a1, u32 a2, u32 a3,
                                         u32 b0, u32 b1) {
    asm volatile(
        "mma.sync.aligned.m16n8k8.row.col.f32.tf32.tf32.f32 "
        "{%0,%1,%2,%3}, {%4,%5,%6,%7}, {%8,%9}, {%0,%1,%2,%3};"
        : "+f"(c[0]), "+f"(c[1]), "+f"(c[2]), "+f"(c[3])
        : "r"(a0), "r"(a1), "r"(a2), "r"(a3), "r"(b0), "r"(b1));
}

__device__ __forceinline__ void cp_async16(u32 dst_smem, const void* src) {
    asm volatile("cp.async.cg.shared.global [%0], [%1], 16;"
                 :: "r"(dst_smem), "l"(src));
}
__device__ __forceinline__ void cp_commit() {
    asm volatile("cp.async.commit_group;");
}
__device__ __forceinline__ void cp_wait_all_groups() {
    asm volatile("cp.async.wait_group 0;");
}

// column permutation for Q: fragment positions tig and tig+4 adjacent -> v2 LDS.
__device__ __forceinline__ int phys_col(int d) {
    return (d & ~7) | ((d & 3) << 1) | ((d >> 2) & 1);
}

// fast exp2 for x <= 0 (poly deg-6, rel err ~1e-5). Handles -1e30 sentinel -> ~0.
__device__ __forceinline__ float fexp2(float x) {
    x = fmaxf(x, -126.0f);
    int ni = __float2int_rd(x);
    float f = x - (float)ni;
    float p = 1.54035304e-4f;
    p = fmaf(p, f, 1.33335581e-3f);
    p = fmaf(p, f, 9.61812911e-3f);
    p = fmaf(p, f, 5.55041087e-2f);
    p = fmaf(p, f, 2.40226507e-1f);
    p = fmaf(p, f, 6.93147181e-1f);
    p = fmaf(p, f, 1.0f);
    return __int_as_float(__float_as_int(p) + (ni << 23));
}

__global__ void __launch_bounds__(NTHREADS, 1)
lminf_kernel(const float* __restrict__ Q, const float* __restrict__ K,
             const float* __restrict__ V, int S) {
    extern __shared__ float sm[];
    float* Qs = sm + QS_OFF;

    const int b   = blockIdx.y;
    const int tid = threadIdx.x;
    const int w    = tid >> 5;
    const int lane = tid & 31;
    const int g    = lane >> 2;   // group id 0..7
    const int tig  = lane & 3;    // thread-in-group 0..3
    const int qb   = 16 * w;      // warp's q-row base within tile
    const int slot = tig & 1;
    const int sA   = (lane & ~3) | (tig >> 1);        // shuffle src for col tig
    const int sB   = sA + 2;                           // shuffle src for col tig+4

    // ---- unit -> (qt, u) mapping: descending qt (LPT: biggest q-tiles first) ----
    const int nQT = S / TQ;
    int qt = 0, u = 0, nt = 0, spq = 1;
    {
        int lin = blockIdx.x;
        int cum = 0;
        for (int t = nQT - 1; t >= 0; t--) {
            int NTt = nt_of(t);
            int kch = (NTt + CHUNK - 1) / CHUNK;
            if (lin - cum < kch) { qt = t; u = lin - cum; nt = NTt; spq = kch; break; }
            cum += kch;
        }
    }
    const int q0 = qt * TQ;

    const float* Qg = Q + (size_t)b * S * D;
    const float* Kg = K + (size_t)b * S * D;
    const float* Vg = V + (size_t)b * S * D;

    const float QSCALE = 0.0883883476f * 1.44269504089f;  // 1/sqrt(128) * log2(e)
    const float LOG2E  = 1.44269504089f;

    // visited = {0,1} (global sinks) ∪ [tLoc, nTile)
    int tLoc = 2;
    {
        int dd = q0 - (LPRE - 1) - TK;
        if (dd >= 0) { int t = dd / TK + 1; if (t > 2) tLoc = t; }
    }
    const int it0 = (u * nt) / spq;
    const int it1 = ((u + 1) * nt) / spq;

    const u32 smem_u32 = (u32)__cvta_generic_to_shared(sm);

    // prefetch K/V tile `it` into buffer (it&1) via cp.async (raw fp32, padded rows)
    auto prefetch = [&](int it) {
        const int k0 = ((it < 2) ? it : (tLoc + it - 2)) * TK;
        const u32 kbuf = smem_u32 + ((it & 1) ? K1_OFF : K0_OFF) * 4;
        const u32 vbuf = smem_u32 + ((it & 1) ? V1_OFF : V0_OFF) * 4;
        const float* ksrc = Kg + (size_t)k0 * D;
        const float* vsrc = Vg + (size_t)k0 * D;
        #pragma unroll
        for (int c = 0; c < (TK * 32) / NTHREADS; c++) {
            int idx = tid + c * NTHREADS;
            int row = idx >> 5, c4 = idx & 31;
            u32 off = (u32)(row * KR_STRIDE + c4 * 4) * 4;
            cp_async16(kbuf + off, ksrc + row * D + c4 * 4);
            cp_async16(vbuf + off, vsrc + row * D + c4 * 4);
        }
        cp_commit();
    };

    if (it0 < it1) {
        prefetch(it0);
        // ---- load Q tile: tf32-rounded, pre-scaled, column-permuted ----
        const float4* src = (const float4*)(Qg + (size_t)q0 * D);
        #pragma unroll
        for (int it = 0; it < (TQ * 32) / NTHREADS; it++) {
            int idx = tid + it * NTHREADS;
            int row = idx >> 5, f4 = idx & 31;
            float4 v = src[idx];
            float vv[4] = {v.x * QSCALE, v.y * QSCALE, v.z * QSCALE, v.w * QSCALE};
            int d0 = f4 * 4;
            #pragma unroll
            for (int e = 0; e < 4; e++)
                Qs[row * QS_STRIDE + phys_col(d0 + e)] = __uint_as_float(to_tf32(vv[e]));
        }
    }

    float co[16][4];              // O accum: 16 dim-tiles x {r0d0,r0d1,r1d0,r1d1}
    #pragma unroll
    for (int ntl = 0; ntl < 16; ntl++)
        #pragma unroll
        for (int e = 0; e < 4; e++) co[ntl][e] = 0.0f;
    float m0 = -1e30f, m1 = -1e30f, l0 = 0.0f, l1 = 0.0f;

    const int i0 = q0 + qb + g;
    const int i1 = i0 + 8;

    for (int it = it0; it < it1; it++) {
        const int k0 = ((it < 2) ? it : (tLoc + it - 2)) * TK;
        const float* Kr = sm + ((it & 1) ? K1_OFF : K0_OFF);
        const float* Vr = sm + ((it & 1) ? V1_OFF : V0_OFF);

        cp_wait_all_groups();      // tile `it` resident
        __syncthreads();           // visible to all warps; prev compute done
        if (it + 1 < it1) prefetch(it + 1);   // overlaps compute below

        // ---- QK^T: 16x64 per warp via 128 HMMA tf32 ----
        float c[8][4];
        #pragma unroll
        for (int ntl = 0; ntl < 8; ntl++)
            #pragma unroll
            for (int e = 0; e < 4; e++) c[ntl][e] = 0.0f;

        #pragma unroll
        for (int kk = 0; kk < 16; kk++) {
            uint2 a02 = *(const uint2*)&Qs[(qb + g)     * QS_STRIDE + 8 * kk + 2 * tig];
            uint2 a13 = *(const uint2*)&Qs[(qb + g + 8) * QS_STRIDE + 8 * kk + 2 * tig];
            #pragma unroll
            for (int ntl = 0; ntl < 8; ntl++) {
                const float* krow = Kr + (8 * ntl + g) * KR_STRIDE + 8 * kk;
                u32 b0 = to_tf32(krow[tig]);
                u32 b1 = to_tf32(krow[tig + 4]);
                mma_tf32(c[ntl], a02.x, a13.x, a02.y, a13.y, b0, b1);
            }
        }

        // ---- mask + bias + online softmax on fragments ----
        float mx0 = -1e30f, mx1 = -1e30f;
        #pragma unroll
        for (int ntl = 0; ntl < 8; ntl++) {
            int j0 = k0 + 8 * ntl + 2 * tig;
            int j1 = j0 + 1;
            bool ok00 = (j0 <= i0) && ((j0 < NGLOBAL) || (j0 >= i0 - (LPRE - 1)));
            bool ok01 = (j1 <= i0) && ((j1 < NGLOBAL) || (j1 >= i0 - (LPRE - 1)));
            bool ok10 = (j0 <= i1) && ((j0 < NGLOBAL) || (j0 >= i1 - (LPRE - 1)));
            bool ok11 = (j1 <= i1) && ((j1 < NGLOBAL) || (j1 >= i1 - (LPRE - 1)));
            c[ntl][0] = ok00 ? fmaf((float)(j0 - i0), LOG2E, c[ntl][0]) : -1e30f;
            c[ntl][1] = ok01 ? fmaf((float)(j1 - i0), LOG2E, c[ntl][1]) : -1e30f;
            c[ntl][2] = ok10 ? fmaf((float)(j0 - i1), LOG2E, c[ntl][2]) : -1e30f;
            c[ntl][3] = ok11 ? fmaf((float)(j1 - i1), LOG2E, c[ntl][3]) : -1e30f;
            mx0 = fmaxf(mx0, fmaxf(c[ntl][0], c[ntl][1]));
            mx1 = fmaxf(mx1, fmaxf(c[ntl][2], c[ntl][3]));
        }
        mx0 = fmaxf(mx0, __shfl_xor_sync(0xffffffffu, mx0, 1));
        mx0 = fmaxf(mx0, __shfl_xor_sync(0xffffffffu, mx0, 2));
        mx1 = fmaxf(mx1, __shfl_xor_sync(0xffffffffu, mx1, 1));
        mx1 = fmaxf(mx1, __shfl_xor_sync(0xffffffffu, mx1, 2));

        float mn0 = fmaxf(m0, mx0), mn1 = fmaxf(m1, mx1);
        float sc0 = fexp2(m0 - mn0), sc1 = fexp2(m1 - mn1);
        float ps0 = 0.0f, ps1 = 0.0f;
        #pragma unroll
        for (int ntl = 0; ntl < 8; ntl++) {
            float p00 = __uint_as_float(to_tf32(fexp2(c[ntl][0] - mn0)));
            float p01 = __uint_as_float(to_tf32(fexp2(c[ntl][1] - mn0)));
            float p10 = __uint_as_float(to_tf32(fexp2(c[ntl][2] - mn1)));
            float p11 = __uint_as_float(to_tf32(fexp2(c[ntl][3] - mn1)));
            ps0 += p00 + p01;
            ps1 += p10 + p11;
            c[ntl][0] = p00; c[ntl][1] = p01; c[ntl][2] = p10; c[ntl][3] = p11;
        }
        ps0 += __shfl_xor_sync(0xffffffffu, ps0, 1);
        ps0 += __shfl_xor_sync(0xffffffffu, ps0, 2);
        ps1 += __shfl_xor_sync(0xffffffffu, ps1, 1);
        ps1 += __shfl_xor_sync(0xffffffffu, ps1, 2);

        l0 = l0 * sc0 + ps0;  m0 = mn0;
        l1 = l1 * sc1 + ps1;  m1 = mn1;
        #pragma unroll
        for (int ntl = 0; ntl < 16; ntl++) {
            co[ntl][0] *= sc0; co[ntl][1] *= sc0;
            co[ntl][2] *= sc1; co[ntl][3] *= sc1;
        }

        // ---- P x V: C-fragment -> A-fragment via intra-quad shuffles, no smem ----
        #pragma unroll
        for (int kt = 0; kt < 8; kt++) {
            // A needs cols {tig, tig+4} of P; C holds cols {2tig, 2tig+1}.
            float v0 = __shfl_sync(0xffffffffu, c[kt][0], sA);
            float v1 = __shfl_sync(0xffffffffu, c[kt][1], sA);
            float v2 = __shfl_sync(0xffffffffu, c[kt][2], sA);
            float v3 = __shfl_sync(0xffffffffu, c[kt][3], sA);
            float w0 = __shfl_sync(0xffffffffu, c[kt][0], sB);
            float w1 = __shfl_sync(0xffffffffu, c[kt][1], sB);
            float w2 = __shfl_sync(0xffffffffu, c[kt][2], sB);
            float w3 = __shfl_sync(0xffffffffu, c[kt][3], sB);
            u32 a0 = __float_as_uint(slot ? v1 : v0);
            u32 a1 = __float_as_uint(slot ? v3 : v2);
            u32 a2 = __float_as_uint(slot ? w1 : w0);
            u32 a3 = __float_as_uint(slot ? w3 : w2);
            #pragma unroll
            for (int ntl = 0; ntl < 16; ntl++) {
                const float* vrow = Vr + (8 * kt + tig) * KR_STRIDE + 8 * ntl + g;
                u32 b0 = to_tf32(vrow[0]);
                u32 b1 = to_tf32(vrow[4 * KR_STRIDE]);
                mma_tf32(co[ntl], a0, a1, a2, a3, b0, b1);
            }
        }
    }

    // ---- epilogue: write unnormalized partials for this split ----
    const size_t rowbase = (size_t)(u * BMAX + b) * S;
    float2* o0 = (float2*)(g_Op + (rowbase + i0) * D);
    float2* o1 = (float2*)(g_Op + (rowbase + i1) * D);
    #pragma unroll
    for (int ntl = 0; ntl < 16; ntl++) {
        o0[4 * ntl + tig] = make_float2(co[ntl][0], co[ntl][1]);
        o1[4 * ntl + tig] = make_float2(co[ntl][2], co[ntl][3]);
    }
    if (tig == 0) {
        g_Ml[rowbase + i0] = m0;  g_Ll[rowbase + i0] = l0;
        g_Ml[rowbase + i1] = m1;  g_Ll[rowbase + i1] = l1;
    }
}

__global__ void __launch_bounds__(256)
combine_kernel(float* __restrict__ O, int S) {
    const int d4pr  = D / 4;                       // float4 per row
    const int total = BMAX * S * d4pr;             // float4 units
    int idx = blockIdx.x * blockDim.x + threadIdx.x;
    if (idx >= total) return;
    int row = idx / d4pr;                          // b*S + i
    int i   = row % S;
    int spq = (nt_of(i / TQ) + CHUNK - 1) / CHUNK; // splits for this row's q-tile

    const size_t rstride = (size_t)BMAX * S;
    float m = -1e30f;
    for (int s = 0; s < spq; s++) {
        float ls = g_Ll[s * rstride + row];
        if (ls > 0.0f) m = fmaxf(m, g_Ml[s * rstride + row]);
    }
    const float4* Op4 = (const float4*)g_Op;
    float denom = 0.0f;
    float4 acc = make_float4(0.0f, 0.0f, 0.0f, 0.0f);
    for (int s = 0; s < spq; s++) {
        float ls = g_Ll[s * rstride + row];
        if (ls > 0.0f) {
            float wv = fexp2(g_Ml[s * rstride + row] - m);
            denom = fmaf(wv, ls, denom);
            float4 o = Op4[(size_t)s * total + idx];
            acc.x = fmaf(wv, o.x, acc.x);
            acc.y = fmaf(wv, o.y, acc.y);
            acc.z = fmaf(wv, o.z, acc.z);
            acc.w = fmaf(wv, o.w, acc.w);
        }
    }
    float inv = 1.0f / denom;
    ((float4*)O)[idx] = make_float4(acc.x * inv, acc.y * inv, acc.z * inv, acc.w * inv);
}

extern "C" void kernel_launch(void* const* d_in, const int* in_sizes, int n_in,
                              void* d_out, int out_size) {
    const float* q = (const float*)d_in[0];
    const float* k = (const float*)d_in[1];
    const float* v = (const float*)d_in[2];
    float* o = (float*)d_out;

    const int B = 2;
    const int S = in_sizes[0] / (B * D);   // 8192
    const int nQT = S / TQ;

    // total uniform work units per batch
    int U = 0;
    for (int t = 0; t < nQT; t++) U += (nt_of(t) + CHUNK - 1) / CHUNK;

    size_t smem_bytes = (size_t)SMEM_FLOATS * sizeof(float);  // ~205 KB
    cudaFuncSetAttribute(lminf_kernel, cudaFuncAttributeMaxDynamicSharedMemorySize,
                         (int)smem_bytes);

    dim3 grid(U, B);
    lminf_kernel<<<grid, NTHREADS, smem_bytes>>>(q, k, v, S);

    int total4 = B * S * (D / 4);
    combine_kernel<<<(total4 + 255) / 256, 256>>>(o, S);
}

// round 9
// speedup vs baseline: 1.0566x; 1.0566x over previous
#include <cuda_runtime.h>
#include <cstdint>

#define D 128
#define TQ 64
#define TK 64
#define NTHREADS 128
#define NGLOBAL 100
#define LPRE 2048
#define SP 4            // key-dimension splits (flash-decoding style)
#define BMAX 2
#define SMAX 8192

#define QS_STRIDE 136   // ≡8 mod 32: conflict-free v2 fragment LDS
#define KR_STRIDE 132   // raw rows padded 128->132 (16B-aligned rows, bank-spread)

#define QS_OFF 0
#define K0_OFF (TQ * QS_STRIDE)            // 8704
#define V0_OFF (K0_OFF + TK * KR_STRIDE)   // 17152
#define SMEM_FLOATS (V0_OFF + TK * KR_STRIDE)   // 25600 floats = 102.4 KB -> 2 CTAs/SM

typedef unsigned int u32;

// split-K scratch (static device globals: allocation-free)
__device__ float g_Op[(size_t)SP * BMAX * SMAX * D];   // unnormalized partial O
__device__ float g_Ml[SP * BMAX * SMAX];               // per-row running max (log2 domain)
__device__ float g_Ll[SP * BMAX * SMAX];               // per-row partial denom

__device__ __forceinline__ u32 to_tf32(float x) {
    u32 r;
    asm("cvt.rna.tf32.f32 %0, %1;" : "=r"(r) : "f"(x));
    return r;
}

__device__ __forceinline__ void mma_tf32(float c[4], u32 a0, u32 a1, u32 a2, u32 a3,
                                         u32 b0, u32 b1) {
    asm volatile(
        "mma.sync.aligned.m16n8k8.row.col.f32.tf32.tf32.f32 "
        "{%0,%1,%2,%3}, {%4,%5,%6,%7}, {%8,%9}, {%0,%1,%2,%3};"
        : "+f"(c[0]), "+f"(c[1]), "+f"(c[2]), "+f"(c[3])
        : "r"(a0), "r"(a1), "r"(a2), "r"(a3), "r"(b0), "r"(b1));
}

__device__ __forceinline__ void cp_async16(u32 dst_smem, const void* src) {
    asm volatile("cp.async.cg.shared.global [%0], [%1], 16;"
                 :: "r"(dst_smem), "l"(src));
}
__device__ __forceinline__ void cp_commit() {
    asm volatile("cp.async.commit_group;");
}
__device__ __forceinline__ void cp_wait_all_groups() {
    asm volatile("cp.async.wait_group 0;");
}

// column permutation for Q: fragment positions tig and tig+4 adjacent -> v2 LDS.
__device__ __forceinline__ int phys_col(int d) {
    return (d & ~7) | ((d & 3) << 1) | ((d >> 2) & 1);
}

// fast exp2 for x <= 0 (poly deg-6, rel err ~1e-5). Handles -1e30 sentinel -> ~0.
__device__ __forceinline__ float fexp2(float x) {
    x = fmaxf(x, -126.0f);
    int ni = __float2int_rd(x);
    float f = x - (float)ni;
    float p = 1.54035304e-4f;
    p = fmaf(p, f, 1.33335581e-3f);
    p = fmaf(p, f, 9.61812911e-3f);
    p = fmaf(p, f, 5.55041087e-2f);
    p = fmaf(p, f, 2.40226507e-1f);
    p = fmaf(p, f, 6.93147181e-1f);
    p = fmaf(p, f, 1.0f);
    return __int_as_float(__float_as_int(p) + (ni << 23));
}

__global__ void __launch_bounds__(NTHREADS, 2)
lminf_kernel(const float* __restrict__ Q, const float* __restrict__ K,
             const float* __restrict__ V, int S) {
    extern __shared__ float sm[];
    float* Qs = sm + QS_OFF;
    float* Kr = sm + K0_OFF;
    float* Vr = sm + V0_OFF;

    const int b   = blockIdx.y;
    const int q0  = blockIdx.x * TQ;
    const int sp  = blockIdx.z;
    const int tid = threadIdx.x;
    const int w    = tid >> 5;
    const int lane = tid & 31;
    const int g    = lane >> 2;   // group id 0..7
    const int tig  = lane & 3;    // thread-in-group 0..3
    const int qb   = 16 * w;      // warp's q-row base within tile (4 warps x 16 = 64)
    const int slot = tig & 1;
    const int sA   = (lane & ~3) | (tig >> 1);        // shuffle src for col tig
    const int sB   = sA + 2;                           // shuffle src for col tig+4

    const float* Qg = Q + (size_t)b * S * D;
    const float* Kg = K + (size_t)b * S * D;
    const float* Vg = V + (size_t)b * S * D;

    const float QSCALE = 0.0883883476f * 1.44269504089f;  // 1/sqrt(128) * log2(e)
    const float LOG2E  = 1.44269504089f;

    // ---- enumerate visited tiles & take this split's contiguous chunk ----
    // visited = {0,1} (global sinks) ∪ [tLoc, nTile)
    const int nTile = (q0 + TQ) / TK;
    int tLoc = 2;
    {
        int dd = q0 - (LPRE - 1) - TK;   // tile t skipped iff t>=2 && 64t <= dd
        if (dd >= 0) { int t = dd / TK + 1; if (t > 2) tLoc = t; }
    }
    int NT = 2 + (nTile - tLoc);
    if (nTile < 2) NT = nTile;           // tiny q0: only causal tiles exist
    const int it0 = (sp * NT) / SP;
    const int it1 = ((sp + 1) * NT) / SP;

    const u32 smem_u32 = (u32)__cvta_generic_to_shared(sm);
    const u32 kbuf = smem_u32 + K0_OFF * 4;
    const u32 vbuf = smem_u32 + V0_OFF * 4;

    // issue async K/V load of tile `it` into the single buffer
    auto load_kv = [&](int it) {
        const int k0 = ((it < 2) ? it : (tLoc + it - 2)) * TK;
        const float* ksrc = Kg + (size_t)k0 * D;
        const float* vsrc = Vg + (size_t)k0 * D;
        #pragma unroll
        for (int c = 0; c < (TK * 32) / NTHREADS; c++) {
            int idx = tid + c * NTHREADS;
            int row = idx >> 5, c4 = idx & 31;
            u32 off = (u32)(row * KR_STRIDE + c4 * 4) * 4;
            cp_async16(kbuf + off, ksrc + row * D + c4 * 4);
            cp_async16(vbuf + off, vsrc + row * D + c4 * 4);
        }
        cp_commit();
    };

    if (it0 < it1) {
        load_kv(it0);   // overlaps with Q load below
        // ---- load Q tile: tf32-rounded, pre-scaled, column-permuted ----
        const float4* src = (const float4*)(Qg + (size_t)q0 * D);
        #pragma unroll
        for (int it = 0; it < (TQ * 32) / NTHREADS; it++) {
            int idx = tid + it * NTHREADS;
            int row = idx >> 5, f4 = idx & 31;
            float4 v = src[idx];
            float vv[4] = {v.x * QSCALE, v.y * QSCALE, v.z * QSCALE, v.w * QSCALE};
            int d0 = f4 * 4;
            #pragma unroll
            for (int e = 0; e < 4; e++)
                Qs[row * QS_STRIDE + phys_col(d0 + e)] = __uint_as_float(to_tf32(vv[e]));
        }
    }

    float co[16][4];              // O accum: 16 dim-tiles x {r0d0,r0d1,r1d0,r1d1}
    #pragma unroll
    for (int nt = 0; nt < 16; nt++)
        #pragma unroll
        for (int e = 0; e < 4; e++) co[nt][e] = 0.0f;
    float m0 = -1e30f, m1 = -1e30f, l0 = 0.0f, l1 = 0.0f;

    const int i0 = q0 + qb + g;
    const int i1 = i0 + 8;

    for (int it = it0; it < it1; it++) {
        const int k0 = ((it < 2) ? it : (tLoc + it - 2)) * TK;

        cp_wait_all_groups();      // tile `it` resident
        __syncthreads();           // visible to all warps

        // ---- QK^T: 16x64 per warp via 128 HMMA tf32 ----
        float c[8][4];
        #pragma unroll
        for (int nt = 0; nt < 8; nt++)
            #pragma unroll
            for (int e = 0; e < 4; e++) c[nt][e] = 0.0f;

        #pragma unroll
        for (int kk = 0; kk < 16; kk++) {
            uint2 a02 = *(const uint2*)&Qs[(qb + g)     * QS_STRIDE + 8 * kk + 2 * tig];
            uint2 a13 = *(const uint2*)&Qs[(qb + g + 8) * QS_STRIDE + 8 * kk + 2 * tig];
            #pragma unroll
            for (int nt = 0; nt < 8; nt++) {
                const float* krow = Kr + (8 * nt + g) * KR_STRIDE + 8 * kk;
                u32 b0 = to_tf32(krow[tig]);
                u32 b1 = to_tf32(krow[tig + 4]);
                mma_tf32(c[nt], a02.x, a13.x, a02.y, a13.y, b0, b1);
            }
        }

        // ---- mask + bias + online softmax on fragments ----
        float mx0 = -1e30f, mx1 = -1e30f;
        #pragma unroll
        for (int nt = 0; nt < 8; nt++) {
            int j0 = k0 + 8 * nt + 2 * tig;
            int j1 = j0 + 1;
            bool ok00 = (j0 <= i0) && ((j0 < NGLOBAL) || (j0 >= i0 - (LPRE - 1)));
            bool ok01 = (j1 <= i0) && ((j1 < NGLOBAL) || (j1 >= i0 - (LPRE - 1)));
            bool ok10 = (j0 <= i1) && ((j0 < NGLOBAL) || (j0 >= i1 - (LPRE - 1)));
            bool ok11 = (j1 <= i1) && ((j1 < NGLOBAL) || (j1 >= i1 - (LPRE - 1)));
            c[nt][0] = ok00 ? fmaf((float)(j0 - i0), LOG2E, c[nt][0]) : -1e30f;
            c[nt][1] = ok01 ? fmaf((float)(j1 - i0), LOG2E, c[nt][1]) : -1e30f;
            c[nt][2] = ok10 ? fmaf((float)(j0 - i1), LOG2E, c[nt][2]) : -1e30f;
            c[nt][3] = ok11 ? fmaf((float)(j1 - i1), LOG2E, c[nt][3]) : -1e30f;
            mx0 = fmaxf(mx0, fmaxf(c[nt][0], c[nt][1]));
            mx1 = fmaxf(mx1, fmaxf(c[nt][2], c[nt][3]));
        }
        mx0 = fmaxf(mx0, __shfl_xor_sync(0xffffffffu, mx0, 1));
        mx0 = fmaxf(mx0, __shfl_xor_sync(0xffffffffu, mx0, 2));
        mx1 = fmaxf(mx1, __shfl_xor_sync(0xffffffffu, mx1, 1));
        mx1 = fmaxf(mx1, __shfl_xor_sync(0xffffffffu, mx1, 2));

        float mn0 = fmaxf(m0, mx0), mn1 = fmaxf(m1, mx1);
        float sc0 = fexp2(m0 - mn0), sc1 = fexp2(m1 - mn1);
        float ps0 = 0.0f, ps1 = 0.0f;
        #pragma unroll
        for (int nt = 0; nt < 8; nt++) {
            float p00 = __uint_as_float(to_tf32(fexp2(c[nt][0] - mn0)));
            float p01 = __uint_as_float(to_tf32(fexp2(c[nt][1] - mn0)));
            float p10 = __uint_as_float(to_tf32(fexp2(c[nt][2] - mn1)));
            float p11 = __uint_as_float(to_tf32(fexp2(c[nt][3] - mn1)));
            ps0 += p00 + p01;
            ps1 += p10 + p11;
            c[nt][0] = p00; c[nt][1] = p01; c[nt][2] = p10; c[nt][3] = p11;
        }
        ps0 += __shfl_xor_sync(0xffffffffu, ps0, 1);
        ps0 += __shfl_xor_sync(0xffffffffu, ps0, 2);
        ps1 += __shfl_xor_sync(0xffffffffu, ps1, 1);
        ps1 += __shfl_xor_sync(0xffffffffu, ps1, 2);

        l0 = l0 * sc0 + ps0;  m0 = mn0;
        l1 = l1 * sc1 + ps1;  m1 = mn1;
        #pragma unroll
        for (int nt = 0; nt < 16; nt++) {
            co[nt][0] *= sc0; co[nt][1] *= sc0;
            co[nt][2] *= sc1; co[nt][3] *= sc1;
        }

        // ---- P x V: C-fragment -> A-fragment via intra-quad shuffles, no smem ----
        #pragma unroll
        for (int kt = 0; kt < 8; kt++) {
            // A needs cols {tig, tig+4} of P; C holds cols {2tig, 2tig+1}.
            float v0 = __shfl_sync(0xffffffffu, c[kt][0], sA);
            float v1 = __shfl_sync(0xffffffffu, c[kt][1], sA);
            float v2 = __shfl_sync(0xffffffffu, c[kt][2], sA);
            float v3 = __shfl_sync(0xffffffffu, c[kt][3], sA);
            float w0 = __shfl_sync(0xffffffffu, c[kt][0], sB);
            float w1 = __shfl_sync(0xffffffffu, c[kt][1], sB);
            float w2 = __shfl_sync(0xffffffffu, c[kt][2], sB);
            float w3 = __shfl_sync(0xffffffffu, c[kt][3], sB);
            u32 a0 = __float_as_uint(slot ? v1 : v0);
            u32 a1 = __float_as_uint(slot ? v3 : v2);
            u32 a2 = __float_as_uint(slot ? w1 : w0);
            u32 a3 = __float_as_uint(slot ? w3 : w2);
            #pragma unroll
            for (int nt = 0; nt < 16; nt++) {
                const float* vrow = Vr + (8 * kt + tig) * KR_STRIDE + 8 * nt + g;
                u32 b0 = to_tf32(vrow[0]);
                u32 b1 = to_tf32(vrow[4 * KR_STRIDE]);
                mma_tf32(co[nt], a0, a1, a2, a3, b0, b1);
            }
        }

        __syncthreads();           // all warps done reading Kr/Vr
        if (it + 1 < it1) load_kv(it + 1);   // refill single buffer
    }

    // ---- epilogue: write unnormalized partials for this split ----
    const size_t rowbase = (size_t)(sp * BMAX + b) * S;
    float2* o0 = (float2*)(g_Op + (rowbase + i0) * D);
    float2* o1 = (float2*)(g_Op + (rowbase + i1) * D);
    #pragma unroll
    for (int nt = 0; nt < 16; nt++) {
        o0[4 * nt + tig] = make_float2(co[nt][0], co[nt][1]);
        o1[4 * nt + tig] = make_float2(co[nt][2], co[nt][3]);
    }
    if (tig == 0) {
        g_Ml[rowbase + i0] = m0;  g_Ll[rowbase + i0] = l0;
        g_Ml[rowbase + i1] = m1;  g_Ll[rowbase + i1] = l1;
    }
}

__global__ void __launch_bounds__(256)
combine_kernel(float* __restrict__ O, int S) {
    const int d4pr  = D / 4;                       // float4 per row
    const int total = BMAX * S * d4pr;             // float4 units
    int idx = blockIdx.x * blockDim.x + threadIdx.x;
    if (idx >= total) return;
    int row = idx / d4pr;                          // b*S + i

    const size_t rstride = (size_t)BMAX * S;
    float ms[SP], ls[SP];
    float m = -1e30f;
    #pragma unroll
    for (int s = 0; s < SP; s++) {
        ms[s] = g_Ml[s * rstride + row];
        ls[s] = g_Ll[s * rstride + row];
        if (ls[s] > 0.0f) m = fmaxf(m, ms[s]);
    }
    const float4* Op4 = (const float4*)g_Op;
    float denom = 0.0f;
    float4 acc = make_float4(0.0f, 0.0f, 0.0f, 0.0f);
    #pragma unroll
    for (int s = 0; s < SP; s++) {
        if (ls[s] > 0.0f) {
            float wv = fexp2(ms[s] - m);
            denom = fmaf(wv, ls[s], denom);
            float4 o = Op4[(size_t)s * total + idx];
            acc.x = fmaf(wv, o.x, acc.x);
            acc.y = fmaf(wv, o.y, acc.y);
            acc.z = fmaf(wv, o.z, acc.z);
            acc.w = fmaf(wv, o.w, acc.w);
        }
    }
    float inv = 1.0f / denom;
    ((float4*)O)[idx] = make_float4(acc.x * inv, acc.y * inv, acc.z * inv, acc.w * inv);
}

extern "C" void kernel_launch(void* const* d_in, const int* in_sizes, int n_in,
                              void* d_out, int out_size) {
    const float* q = (const float*)d_in[0];
    const float* k = (const float*)d_in[1];
    const float* v = (const float*)d_in[2];
    float* o = (float*)d_out;

    const int B = 2;
    const int S = in_sizes[0] / (B * D);   // 8192

    size_t smem_bytes = (size_t)SMEM_FLOATS * sizeof(float);  // 102.4 KB -> 2 CTAs/SM
    cudaFuncSetAttribute(lminf_kernel, cudaFuncAttributeMaxDynamicSharedMemorySize,
                         (int)smem_bytes);

    dim3 grid(S / TQ, B, SP);
    lminf_kernel<<<grid, NTHREADS, smem_bytes>>>(q, k, v, S);

    int total4 = B * S * (D / 4);
    combine_kernel<<<(total4 + 255) / 256, 256>>>(o, S);
}

// round 10
// speedup vs baseline: 1.4548x; 1.3769x over previous
#include <cuda_runtime.h>
#include <cstdint>

#define D 128
#define TQ 64
#define TK 64
#define NTHREADS 128
#define NGLOBAL 100
#define LPRE 2048
#define SP 4            // key-dimension splits (flash-decoding style)
#define BMAX 2
#define SMAX 8192

#define QS_STRIDE 136   // ≡8 mod 32: conflict-free v2 fragment LDS
#define KS_STRIDE 136   // ≡8 mod 32: conflict-free v2 fragment LDS
#define VS_STRIDE 132   // ≡4 mod 32: conflict-free scalar V loads (rows 2tig, +1)

#define QS_OFF 0
#define K0_OFF (TQ * QS_STRIDE)            // 8704
#define V0_OFF (K0_OFF + TK * KS_STRIDE)   // 17408
#define SMEM_FLOATS (V0_OFF + TK * VS_STRIDE)   // 25856 floats = 103.4 KB -> 2 CTAs/SM

typedef unsigned int u32;

// split-K scratch (static device globals: allocation-free)
__device__ float g_Op[(size_t)SP * BMAX * SMAX * D];   // unnormalized partial O
__device__ float g_Ml[SP * BMAX * SMAX];               // per-row running max (log2 domain)
__device__ float g_Ll[SP * BMAX * SMAX];               // per-row partial denom

// k-slot remap: slot tig <-> logical dim 2tig, slot tig+4 <-> 2tig+1 (consistent
// across A and B, so the MMA contraction is unchanged). Lets A/B frags come from
// RAW row layouts with vector loads, and makes QK's C-frag directly a PV A-frag.
__device__ __forceinline__ void mma_tf32(float c[4], u32 a0, u32 a1, u32 a2, u32 a3,
                                         u32 b0, u32 b1) {
    asm volatile(
        "mma.sync.aligned.m16n8k8.row.col.f32.tf32.tf32.f32 "
        "{%0,%1,%2,%3}, {%4,%5,%6,%7}, {%8,%9}, {%0,%1,%2,%3};"
        : "+f"(c[0]), "+f"(c[1]), "+f"(c[2]), "+f"(c[3])
        : "r"(a0), "r"(a1), "r"(a2), "r"(a3), "r"(b0), "r"(b1));
}

__device__ __forceinline__ void cp_async16(u32 dst_smem, const void* src) {
    asm volatile("cp.async.cg.shared.global [%0], [%1], 16;"
                 :: "r"(dst_smem), "l"(src));
}
__device__ __forceinline__ void cp_commit() {
    asm volatile("cp.async.commit_group;");
}
__device__ __forceinline__ void cp_wait_all_groups() {
    asm volatile("cp.async.wait_group 0;");
}

// fast exp2 for x <= 0 (poly deg-6, rel err ~1e-5). Handles -1e30 sentinel -> ~0.
__device__ __forceinline__ float fexp2(float x) {
    x = fmaxf(x, -126.0f);
    int ni = __float2int_rd(x);
    float f = x - (float)ni;
    float p = 1.54035304e-4f;
    p = fmaf(p, f, 1.33335581e-3f);
    p = fmaf(p, f, 9.61812911e-3f);
    p = fmaf(p, f, 5.55041087e-2f);
    p = fmaf(p, f, 2.40226507e-1f);
    p = fmaf(p, f, 6.93147181e-1f);
    p = fmaf(p, f, 1.0f);
    return __int_as_float(__float_as_int(p) + (ni << 23));
}

__global__ void __launch_bounds__(NTHREADS, 2)
lminf_kernel(const float* __restrict__ Q, const float* __restrict__ K,
             const float* __restrict__ V, int S) {
    extern __shared__ float sm[];
    float* Qs = sm + QS_OFF;
    float* Kr = sm + K0_OFF;
    float* Vr = sm + V0_OFF;

    const int b   = blockIdx.y;
    const int q0  = blockIdx.x * TQ;
    const int sp  = blockIdx.z;
    const int tid = threadIdx.x;
    const int w    = tid >> 5;
    const int lane = tid & 31;
    const int g    = lane >> 2;   // group id 0..7
    const int tig  = lane & 3;    // thread-in-group 0..3
    const int qb   = 16 * w;      // warp's q-row base within tile (4 warps x 16 = 64)

    const float* Qg = Q + (size_t)b * S * D;
    const float* Kg = K + (size_t)b * S * D;
    const float* Vg = V + (size_t)b * S * D;

    const float QSC2  = 0.0883883476f * 1.44269504089f;  // 1/sqrt(128) * log2(e)
    const float LOG2E = 1.44269504089f;

    // ---- enumerate visited tiles & take this split's contiguous chunk ----
    // visited = {0,1} (global sinks) ∪ [tLoc, nTile)
    const int nTile = (q0 + TQ) / TK;
    int tLoc = 2;
    {
        int dd = q0 - (LPRE - 1) - TK;   // tile t skipped iff t>=2 && 64t <= dd
        if (dd >= 0) { int t = dd / TK + 1; if (t > 2) tLoc = t; }
    }
    int NT = 2 + (nTile - tLoc);
    if (nTile < 2) NT = nTile;           // tiny q0: only causal tiles exist
    const int it0 = (sp * NT) / SP;
    const int it1 = ((sp + 1) * NT) / SP;

    const u32 smem_u32 = (u32)__cvta_generic_to_shared(sm);
    const u32 qbuf = smem_u32 + QS_OFF * 4;
    const u32 kbuf = smem_u32 + K0_OFF * 4;
    const u32 vbuf = smem_u32 + V0_OFF * 4;

    // issue async K/V load of tile `it` into the single buffer (raw rows, padded)
    auto load_kv = [&](int it) {
        const int k0 = ((it < 2) ? it : (tLoc + it - 2)) * TK;
        const float* ksrc = Kg + (size_t)k0 * D;
        const float* vsrc = Vg + (size_t)k0 * D;
        #pragma unroll
        for (int c = 0; c < (TK * 32) / NTHREADS; c++) {
            int idx = tid + c * NTHREADS;
            int row = idx >> 5, c4 = idx & 31;
            cp_async16(kbuf + (u32)(row * KS_STRIDE + c4 * 4) * 4, ksrc + row * D + c4 * 4);
            cp_async16(vbuf + (u32)(row * VS_STRIDE + c4 * 4) * 4, vsrc + row * D + c4 * 4);
        }
        cp_commit();
    };

    if (it0 < it1) {
        // Q raw via cp.async too (scale folded into softmax) + first K/V tile
        const float* qsrc = Qg + (size_t)q0 * D;
        #pragma unroll
        for (int c = 0; c < (TQ * 32) / NTHREADS; c++) {
            int idx = tid + c * NTHREADS;
            int row = idx >> 5, c4 = idx & 31;
            cp_async16(qbuf + (u32)(row * QS_STRIDE + c4 * 4) * 4, qsrc + row * D + c4 * 4);
        }
        load_kv(it0);
    }

    float co[16][4];              // O accum: 16 dim-tiles x {r0d0,r0d1,r1d0,r1d1}
    #pragma unroll
    for (int nt = 0; nt < 16; nt++)
        #pragma unroll
        for (int e = 0; e < 4; e++) co[nt][e] = 0.0f;
    float m0 = -1e30f, m1 = -1e30f, l0 = 0.0f, l1 = 0.0f;

    const int i0 = q0 + qb + g;
    const int i1 = i0 + 8;

    for (int it = it0; it < it1; it++) {
        const int k0 = ((it < 2) ? it : (tLoc + it - 2)) * TK;

        cp_wait_all_groups();      // tile `it` (and Q on first iter) resident
        __syncthreads();           // visible to all warps

        // ---- QK^T: 16x64 per warp; k-slot remap -> raw-layout v2 frags, no cvt ----
        float c[8][4];
        #pragma unroll
        for (int nt = 0; nt < 8; nt++)
            #pragma unroll
            for (int e = 0; e < 4; e++) c[nt][e] = 0.0f;

        #pragma unroll
        for (int kk = 0; kk < 16; kk++) {
            uint2 a02 = *(const uint2*)&Qs[(qb + g)     * QS_STRIDE + 8 * kk + 2 * tig];
            uint2 a13 = *(const uint2*)&Qs[(qb + g + 8) * QS_STRIDE + 8 * kk + 2 * tig];
            #pragma unroll
            for (int nt = 0; nt < 8; nt++) {
                uint2 b01 = *(const uint2*)&Kr[(8 * nt + g) * KS_STRIDE + 8 * kk + 2 * tig];
                mma_tf32(c[nt], a02.x, a13.x, a02.y, a13.y, b01.x, b01.y);
            }
        }

        // ---- mask + bias + online softmax (scale folded here) ----
        float mx0 = -1e30f, mx1 = -1e30f;
        #pragma unroll
        for (int nt = 0; nt < 8; nt++) {
            int j0 = k0 + 8 * nt + 2 * tig;
            int j1 = j0 + 1;
            bool ok00 = (j0 <= i0) && ((j0 < NGLOBAL) || (j0 >= i0 - (LPRE - 1)));
            bool ok01 = (j1 <= i0) && ((j1 < NGLOBAL) || (j1 >= i0 - (LPRE - 1)));
            bool ok10 = (j0 <= i1) && ((j0 < NGLOBAL) || (j0 >= i1 - (LPRE - 1)));
            bool ok11 = (j1 <= i1) && ((j1 < NGLOBAL) || (j1 >= i1 - (LPRE - 1)));
            c[nt][0] = ok00 ? fmaf(c[nt][0], QSC2, (float)(j0 - i0) * LOG2E) : -1e30f;
            c[nt][1] = ok01 ? fmaf(c[nt][1], QSC2, (float)(j1 - i0) * LOG2E) : -1e30f;
            c[nt][2] = ok10 ? fmaf(c[nt][2], QSC2, (float)(j0 - i1) * LOG2E) : -1e30f;
            c[nt][3] = ok11 ? fmaf(c[nt][3], QSC2, (float)(j1 - i1) * LOG2E) : -1e30f;
            mx0 = fmaxf(mx0, fmaxf(c[nt][0], c[nt][1]));
            mx1 = fmaxf(mx1, fmaxf(c[nt][2], c[nt][3]));
        }
        mx0 = fmaxf(mx0, __shfl_xor_sync(0xffffffffu, mx0, 1));
        mx0 = fmaxf(mx0, __shfl_xor_sync(0xffffffffu, mx0, 2));
        mx1 = fmaxf(mx1, __shfl_xor_sync(0xffffffffu, mx1, 1));
        mx1 = fmaxf(mx1, __shfl_xor_sync(0xffffffffu, mx1, 2));

        float mn0 = fmaxf(m0, mx0), mn1 = fmaxf(m1, mx1);
        float sc0 = fexp2(m0 - mn0), sc1 = fexp2(m1 - mn1);
        float ps0 = 0.0f, ps1 = 0.0f;
        #pragma unroll
        for (int nt = 0; nt < 8; nt++) {
            float p00 = fexp2(c[nt][0] - mn0);
            float p01 = fexp2(c[nt][1] - mn0);
            float p10 = fexp2(c[nt][2] - mn1);
            float p11 = fexp2(c[nt][3] - mn1);
            ps0 += p00 + p01;
            ps1 += p10 + p11;
            c[nt][0] = p00; c[nt][1] = p01; c[nt][2] = p10; c[nt][3] = p11;
        }
        ps0 += __shfl_xor_sync(0xffffffffu, ps0, 1);
        ps0 += __shfl_xor_sync(0xffffffffu, ps0, 2);
        ps1 += __shfl_xor_sync(0xffffffffu, ps1, 1);
        ps1 += __shfl_xor_sync(0xffffffffu, ps1, 2);

        l0 = l0 * sc0 + ps0;  m0 = mn0;
        l1 = l1 * sc1 + ps1;  m1 = mn1;
        #pragma unroll
        for (int nt = 0; nt < 16; nt++) {
            co[nt][0] *= sc0; co[nt][1] *= sc0;
            co[nt][2] *= sc1; co[nt][3] *= sc1;
        }

        // ---- P x V: C-frag IS the A-frag under the k-slot remap (no shuffles) ----
        #pragma unroll
        for (int kt = 0; kt < 8; kt++) {
            u32 a0 = __float_as_uint(c[kt][0]);   // row g,   slot tig   (= logical 2tig)
            u32 a1 = __float_as_uint(c[kt][2]);   // row g+8, slot tig
            u32 a2 = __float_as_uint(c[kt][1]);   // row g,   slot tig+4 (= logical 2tig+1)
            u32 a3 = __float_as_uint(c[kt][3]);   // row g+8, slot tig+4
            const float* vrow = Vr + (8 * kt + 2 * tig) * VS_STRIDE + g;
            #pragma unroll
            for (int nt = 0; nt < 16; nt++) {
                u32 b0 = __float_as_uint(vrow[8 * nt]);              // V[2tig][d]
                u32 b1 = __float_as_uint(vrow[VS_STRIDE + 8 * nt]);  // V[2tig+1][d]
                mma_tf32(co[nt], a0, a1, a2, a3, b0, b1);
            }
        }

        __syncthreads();           // all warps done reading Kr/Vr
        if (it + 1 < it1) load_kv(it + 1);   // refill single buffer
    }

    // ---- epilogue: write unnormalized partials for this split ----
    const size_t rowbase = (size_t)(sp * BMAX + b) * S;
    float2* o0 = (float2*)(g_Op + (rowbase + i0) * D);
    float2* o1 = (float2*)(g_Op + (rowbase + i1) * D);
    #pragma unroll
    for (int nt = 0; nt < 16; nt++) {
        o0[4 * nt + tig] = make_float2(co[nt][0], co[nt][1]);
        o1[4 * nt + tig] = make_float2(co[nt][2], co[nt][3]);
    }
    if (tig == 0) {
        g_Ml[rowbase + i0] = m0;  g_Ll[rowbase + i0] = l0;
        g_Ml[rowbase + i1] = m1;  g_Ll[rowbase + i1] = l1;
    }
}

__global__ void __launch_bounds__(256)
combine_kernel(float* __restrict__ O, int S) {
    const int d4pr  = D / 4;                       // float4 per row
    const int total = BMAX * S * d4pr;             // float4 units
    int idx = blockIdx.x * blockDim.x + threadIdx.x;
    if (idx >= total) return;
    int row = idx / d4pr;                          // b*S + i

    const size_t rstride = (size_t)BMAX * S;
    float ms[SP], ls[SP];
    float m = -1e30f;
    #pragma unroll
    for (int s = 0; s < SP; s++) {
        ms[s] = g_Ml[s * rstride + row];
        ls[s] = g_Ll[s * rstride + row];
        if (ls[s] > 0.0f) m = fmaxf(m, ms[s]);
    }
    const float4* Op4 = (const float4*)g_Op;
    float denom = 0.0f;
    float4 acc = make_float4(0.0f, 0.0f, 0.0f, 0.0f);
    #pragma unroll
    for (int s = 0; s < SP; s++) {
        if (ls[s] > 0.0f) {
            float wv = fexp2(ms[s] - m);
            denom = fmaf(wv, ls[s], denom);
            float4 o = Op4[(size_t)s * total + idx];
            acc.x = fmaf(wv, o.x, acc.x);
            acc.y = fmaf(wv, o.y, acc.y);
            acc.z = fmaf(wv, o.z, acc.z);
            acc.w = fmaf(wv, o.w, acc.w);
        }
    }
    float inv = 1.0f / denom;
    ((float4*)O)[idx] = make_float4(acc.x * inv, acc.y * inv, acc.z * inv, acc.w * inv);
}

extern "C" void kernel_launch(void* const* d_in, const int* in_sizes, int n_in,
                              void* d_out, int out_size) {
    const float* q = (const float*)d_in[0];
    const float* k = (const float*)d_in[1];
    const float* v = (const float*)d_in[2];
    float* o = (float*)d_out;

    const int B = 2;
    const int S = in_sizes[0] / (B * D);   // 8192

    size_t smem_bytes = (size_t)SMEM_FLOATS * sizeof(float);  // 103.4 KB -> 2 CTAs/SM
    cudaFuncSetAttribute(lminf_kernel, cudaFuncAttributeMaxDynamicSharedMemorySize,
                         (int)smem_bytes);

    dim3 grid(S / TQ, B, SP);
    lminf_kernel<<<grid, NTHREADS, smem_bytes>>>(q, k, v, S);

    int total4 = B * S * (D / 4);
    combine_kernel<<<(total4 + 255) / 256, 256>>>(o, S);
}

// round 11
// speedup vs baseline: 1.7653x; 1.2134x over previous
#include <cuda_runtime.h>
#include <cstdint>

#define D 128
#define TQ 64
#define TK 64
#define NTHREADS 128
#define NGLOBAL 100
#define LPRE 2048
#define SP 4            // key-dimension splits (flash-decoding style)
#define BMAX 2
#define SMAX 8192

#define QS_STRIDE 136   // ≡8 mod 32: conflict-free v2 fragment LDS
#define KS_STRIDE 136   // ≡8 mod 32: conflict-free v2 fragment LDS
#define VS_STRIDE 132   // ≡4 mod 32: conflict-free scalar V loads (rows 2tig, +1)

#define QS_OFF 0
#define K0_OFF (TQ * QS_STRIDE)            // 8704
#define V0_OFF (K0_OFF + TK * KS_STRIDE)   // 17408
#define SMEM_FLOATS (V0_OFF + TK * VS_STRIDE)   // 25856 floats = 103.4 KB -> 2 CTAs/SM

typedef unsigned int u32;

// split-K scratch (static device globals: allocation-free)
__device__ float g_Op[(size_t)SP * BMAX * SMAX * D];   // unnormalized partial O
__device__ float g_Ml[SP * BMAX * SMAX];               // per-row running max (log2 domain)
__device__ float g_Ll[SP * BMAX * SMAX];               // per-row partial denom

// k-slot remap: slot tig <-> logical dim 2tig, slot tig+4 <-> 2tig+1 (consistent
// across A and B, so the MMA contraction is unchanged). Lets A/B frags come from
// RAW row layouts with vector loads, and makes QK's C-frag directly a PV A-frag.
__device__ __forceinline__ void mma_tf32(float c[4], u32 a0, u32 a1, u32 a2, u32 a3,
                                         u32 b0, u32 b1) {
    asm volatile(
        "mma.sync.aligned.m16n8k8.row.col.f32.tf32.tf32.f32 "
        "{%0,%1,%2,%3}, {%4,%5,%6,%7}, {%8,%9}, {%0,%1,%2,%3};"
        : "+f"(c[0]), "+f"(c[1]), "+f"(c[2]), "+f"(c[3])
        : "r"(a0), "r"(a1), "r"(a2), "r"(a3), "r"(b0), "r"(b1));
}

__device__ __forceinline__ void cp_async16(u32 dst_smem, const void* src) {
    asm volatile("cp.async.cg.shared.global [%0], [%1], 16;"
                 :: "r"(dst_smem), "l"(src));
}
__device__ __forceinline__ void cp_commit() {
    asm volatile("cp.async.commit_group;");
}
__device__ __forceinline__ void cp_wait_1() {   // allow 1 group outstanding
    asm volatile("cp.async.wait_group 1;");
}
__device__ __forceinline__ void cp_wait_0() {   // all groups done
    asm volatile("cp.async.wait_group 0;");
}

// fast exp2 for x <= 0 (poly deg-6, rel err ~1e-5). Handles -1e30 sentinel -> ~0.
__device__ __forceinline__ float fexp2(float x) {
    x = fmaxf(x, -126.0f);
    int ni = __float2int_rd(x);
    float f = x - (float)ni;
    float p = 1.54035304e-4f;
    p = fmaf(p, f, 1.33335581e-3f);
    p = fmaf(p, f, 9.61812911e-3f);
    p = fmaf(p, f, 5.55041087e-2f);
    p = fmaf(p, f, 2.40226507e-1f);
    p = fmaf(p, f, 6.93147181e-1f);
    p = fmaf(p, f, 1.0f);
    return __int_as_float(__float_as_int(p) + (ni << 23));
}

__global__ void __launch_bounds__(NTHREADS, 2)
lminf_kernel(const float* __restrict__ Q, const float* __restrict__ K,
             const float* __restrict__ V, int S) {
    extern __shared__ float sm[];
    float* Qs = sm + QS_OFF;
    float* Kr = sm + K0_OFF;
    float* Vr = sm + V0_OFF;

    const int b   = blockIdx.y;
    const int q0  = blockIdx.x * TQ;
    const int sp  = blockIdx.z;
    const int tid = threadIdx.x;
    const int w    = tid >> 5;
    const int lane = tid & 31;
    const int g    = lane >> 2;   // group id 0..7
    const int tig  = lane & 3;    // thread-in-group 0..3
    const int qb   = 16 * w;      // warp's q-row base within tile (4 warps x 16 = 64)

    const float* Qg = Q + (size_t)b * S * D;
    const float* Kg = K + (size_t)b * S * D;
    const float* Vg = V + (size_t)b * S * D;

    const float QSC2  = 0.0883883476f * 1.44269504089f;  // 1/sqrt(128) * log2(e)
    const float LOG2E = 1.44269504089f;

    // ---- enumerate visited tiles & take this split's contiguous chunk ----
    // visited = {0,1} (global sinks) ∪ [tLoc, nTile)
    const int nTile = (q0 + TQ) / TK;
    int tLoc = 2;
    {
        int dd = q0 - (LPRE - 1) - TK;   // tile t skipped iff t>=2 && 64t <= dd
        if (dd >= 0) { int t = dd / TK + 1; if (t > 2) tLoc = t; }
    }
    int NT = 2 + (nTile - tLoc);
    if (nTile < 2) NT = nTile;           // tiny q0: only causal tiles exist
    const int it0 = (sp * NT) / SP;
    const int it1 = ((sp + 1) * NT) / SP;

    const u32 smem_u32 = (u32)__cvta_generic_to_shared(sm);
    const u32 qbuf = smem_u32 + QS_OFF * 4;
    const u32 kbuf = smem_u32 + K0_OFF * 4;
    const u32 vbuf = smem_u32 + V0_OFF * 4;

    auto k0_of = [&](int it) { return ((it < 2) ? it : (tLoc + it - 2)) * TK; };

    // separate K / V loads, each its own commit group
    auto load_k = [&](int it) {
        const float* ksrc = Kg + (size_t)k0_of(it) * D;
        #pragma unroll
        for (int c = 0; c < (TK * 32) / NTHREADS; c++) {
            int idx = tid + c * NTHREADS;
            int row = idx >> 5, c4 = idx & 31;
            cp_async16(kbuf + (u32)(row * KS_STRIDE + c4 * 4) * 4, ksrc + row * D + c4 * 4);
        }
        cp_commit();
    };
    auto load_v = [&](int it) {
        const float* vsrc = Vg + (size_t)k0_of(it) * D;
        #pragma unroll
        for (int c = 0; c < (TK * 32) / NTHREADS; c++) {
            int idx = tid + c * NTHREADS;
            int row = idx >> 5, c4 = idx & 31;
            cp_async16(vbuf + (u32)(row * VS_STRIDE + c4 * 4) * 4, vsrc + row * D + c4 * 4);
        }
        cp_commit();
    };

    if (it0 < it1) {
        // group 1: Q + K(it0); group 2: V(it0)
        const float* qsrc = Qg + (size_t)q0 * D;
        #pragma unroll
        for (int c = 0; c < (TQ * 32) / NTHREADS; c++) {
            int idx = tid + c * NTHREADS;
            int row = idx >> 5, c4 = idx & 31;
            cp_async16(qbuf + (u32)(row * QS_STRIDE + c4 * 4) * 4, qsrc + row * D + c4 * 4);
        }
        {
            const float* ksrc = Kg + (size_t)k0_of(it0) * D;
            #pragma unroll
            for (int c = 0; c < (TK * 32) / NTHREADS; c++) {
                int idx = tid + c * NTHREADS;
                int row = idx >> 5, c4 = idx & 31;
                cp_async16(kbuf + (u32)(row * KS_STRIDE + c4 * 4) * 4, ksrc + row * D + c4 * 4);
            }
        }
        cp_commit();
        load_v(it0);
    }

    float co[16][4];              // O accum: 16 dim-tiles x {r0d0,r0d1,r1d0,r1d1}
    #pragma unroll
    for (int nt = 0; nt < 16; nt++)
        #pragma unroll
        for (int e = 0; e < 4; e++) co[nt][e] = 0.0f;
    float m0 = -1e30f, m1 = -1e30f, l0 = 0.0f, l1 = 0.0f;

    const int i0 = q0 + qb + g;
    const int i1 = i0 + 8;

    for (int it = it0; it < it1; it++) {
        const int k0 = k0_of(it);

        // pending at top: {K(it) or Q+K(it), V(it)} -> wait(1) retires K group
        cp_wait_1();
        __syncthreads();

        // ---- QK^T: 16x64 per warp; k-slot remap -> raw-layout v2 frags, no cvt ----
        float c[8][4];
        #pragma unroll
        for (int nt = 0; nt < 8; nt++)
            #pragma unroll
            for (int e = 0; e < 4; e++) c[nt][e] = 0.0f;

        #pragma unroll
        for (int kk = 0; kk < 16; kk++) {
            uint2 a02 = *(const uint2*)&Qs[(qb + g)     * QS_STRIDE + 8 * kk + 2 * tig];
            uint2 a13 = *(const uint2*)&Qs[(qb + g + 8) * QS_STRIDE + 8 * kk + 2 * tig];
            #pragma unroll
            for (int nt = 0; nt < 8; nt++) {
                uint2 b01 = *(const uint2*)&Kr[(8 * nt + g) * KS_STRIDE + 8 * kk + 2 * tig];
                mma_tf32(c[nt], a02.x, a13.x, a02.y, a13.y, b01.x, b01.y);
            }
        }

        __syncthreads();                    // all warps done reading Kr
        if (it + 1 < it1) load_k(it + 1);   // refill K; covered by softmax+PV

        // ---- mask + bias + online softmax ----
        // interior tile (fully allowed): causal strictly below diagonal AND
        // (inside local window for all rows, or the all-global tile k0==0)
        const bool interior =
            (k0 + TK <= q0) && ((k0 >= q0 + TQ - LPRE) || (k0 == 0));

        float mx0 = -1e30f, mx1 = -1e30f;
        if (interior) {
            const float bias00 = (float)(k0 - i0) * LOG2E;   // + (8nt+2tig+e)*LOG2E
            const float bias1  = (float)(k0 - i1) * LOG2E;
            #pragma unroll
            for (int nt = 0; nt < 8; nt++) {
                float d0 = (float)(8 * nt + 2 * tig);
                c[nt][0] = fmaf(c[nt][0], QSC2, fmaf(d0,        LOG2E, bias00));
                c[nt][1] = fmaf(c[nt][1], QSC2, fmaf(d0 + 1.0f, LOG2E, bias00));
                c[nt][2] = fmaf(c[nt][2], QSC2, fmaf(d0,        LOG2E, bias1));
                c[nt][3] = fmaf(c[nt][3], QSC2, fmaf(d0 + 1.0f, LOG2E, bias1));
                mx0 = fmaxf(mx0, fmaxf(c[nt][0], c[nt][1]));
                mx1 = fmaxf(mx1, fmaxf(c[nt][2], c[nt][3]));
            }
        } else {
            #pragma unroll
            for (int nt = 0; nt < 8; nt++) {
                int j0 = k0 + 8 * nt + 2 * tig;
                int j1 = j0 + 1;
                bool ok00 = (j0 <= i0) && ((j0 < NGLOBAL) || (j0 >= i0 - (LPRE - 1)));
                bool ok01 = (j1 <= i0) && ((j1 < NGLOBAL) || (j1 >= i0 - (LPRE - 1)));
                bool ok10 = (j0 <= i1) && ((j0 < NGLOBAL) || (j0 >= i1 - (LPRE - 1)));
                bool ok11 = (j1 <= i1) && ((j1 < NGLOBAL) || (j1 >= i1 - (LPRE - 1)));
                c[nt][0] = ok00 ? fmaf(c[nt][0], QSC2, (float)(j0 - i0) * LOG2E) : -1e30f;
                c[nt][1] = ok01 ? fmaf(c[nt][1], QSC2, (float)(j1 - i0) * LOG2E) : -1e30f;
                c[nt][2] = ok10 ? fmaf(c[nt][2], QSC2, (float)(j0 - i1) * LOG2E) : -1e30f;
                c[nt][3] = ok11 ? fmaf(c[nt][3], QSC2, (float)(j1 - i1) * LOG2E) : -1e30f;
                mx0 = fmaxf(mx0, fmaxf(c[nt][0], c[nt][1]));
                mx1 = fmaxf(mx1, fmaxf(c[nt][2], c[nt][3]));
            }
        }
        mx0 = fmaxf(mx0, __shfl_xor_sync(0xffffffffu, mx0, 1));
        mx0 = fmaxf(mx0, __shfl_xor_sync(0xffffffffu, mx0, 2));
        mx1 = fmaxf(mx1, __shfl_xor_sync(0xffffffffu, mx1, 1));
        mx1 = fmaxf(mx1, __shfl_xor_sync(0xffffffffu, mx1, 2));

        float mn0 = fmaxf(m0, mx0), mn1 = fmaxf(m1, mx1);
        float sc0 = fexp2(m0 - mn0), sc1 = fexp2(m1 - mn1);
        float ps0 = 0.0f, ps1 = 0.0f;
        #pragma unroll
        for (int nt = 0; nt < 8; nt++) {
            float p00 = fexp2(c[nt][0] - mn0);
            float p01 = fexp2(c[nt][1] - mn0);
            float p10 = fexp2(c[nt][2] - mn1);
            float p11 = fexp2(c[nt][3] - mn1);
            ps0 += p00 + p01;
            ps1 += p10 + p11;
            c[nt][0] = p00; c[nt][1] = p01; c[nt][2] = p10; c[nt][3] = p11;
        }
        ps0 += __shfl_xor_sync(0xffffffffu, ps0, 1);
        ps0 += __shfl_xor_sync(0xffffffffu, ps0, 2);
        ps1 += __shfl_xor_sync(0xffffffffu, ps1, 1);
        ps1 += __shfl_xor_sync(0xffffffffu, ps1, 2);

        l0 = l0 * sc0 + ps0;  m0 = mn0;
        l1 = l1 * sc1 + ps1;  m1 = mn1;
        #pragma unroll
        for (int nt = 0; nt < 16; nt++) {
            co[nt][0] *= sc0; co[nt][1] *= sc0;
            co[nt][2] *= sc1; co[nt][3] *= sc1;
        }

        // V(it) arrival: pending {V(it), K(it+1)} -> wait(1); last iter: wait(0)
        if (it + 1 < it1) cp_wait_1(); else cp_wait_0();
        __syncthreads();

        // ---- P x V: C-frag IS the A-frag under the k-slot remap (no shuffles) ----
        #pragma unroll
        for (int kt = 0; kt < 8; kt++) {
            u32 a0 = __float_as_uint(c[kt][0]);   // row g,   slot tig   (= logical 2tig)
            u32 a1 = __float_as_uint(c[kt][2]);   // row g+8, slot tig
            u32 a2 = __float_as_uint(c[kt][1]);   // row g,   slot tig+4 (= logical 2tig+1)
            u32 a3 = __float_as_uint(c[kt][3]);   // row g+8, slot tig+4
            const float* vrow = Vr + (8 * kt + 2 * tig) * VS_STRIDE + g;
            #pragma unroll
            for (int nt = 0; nt < 16; nt++) {
                u32 b0 = __float_as_uint(vrow[8 * nt]);              // V[2tig][d]
                u32 b1 = __float_as_uint(vrow[VS_STRIDE + 8 * nt]);  // V[2tig+1][d]
                mma_tf32(co[nt], a0, a1, a2, a3, b0, b1);
            }
        }

        __syncthreads();                    // all warps done reading Vr
        if (it + 1 < it1) load_v(it + 1);   // refill V; covered by next QK+softmax
    }

    // ---- epilogue: write unnormalized partials for this split ----
    const size_t rowbase = (size_t)(sp * BMAX + b) * S;
    float2* o0 = (float2*)(g_Op + (rowbase + i0) * D);
    float2* o1 = (float2*)(g_Op + (rowbase + i1) * D);
    #pragma unroll
    for (int nt = 0; nt < 16; nt++) {
        o0[4 * nt + tig] = make_float2(co[nt][0], co[nt][1]);
        o1[4 * nt + tig] = make_float2(co[nt][2], co[nt][3]);
    }
    if (tig == 0) {
        g_Ml[rowbase + i0] = m0;  g_Ll[rowbase + i0] = l0;
        g_Ml[rowbase + i1] = m1;  g_Ll[rowbase + i1] = l1;
    }
}

__global__ void __launch_bounds__(256)
combine_kernel(float* __restrict__ O, int S) {
    const int d4pr  = D / 4;                       // float4 per row
    const int total = BMAX * S * d4pr;             // float4 units
    int idx = blockIdx.x * blockDim.x + threadIdx.x;
    if (idx >= total) return;
    int row = idx / d4pr;                          // b*S + i

    const size_t rstride = (size_t)BMAX * S;
    float ms[SP], ls[SP];
    float m = -1e30f;
    #pragma unroll
    for (int s = 0; s < SP; s++) {
        ms[s] = g_Ml[s * rstride + row];
        ls[s] = g_Ll[s * rstride + row];
        if (ls[s] > 0.0f) m = fmaxf(m, ms[s]);
    }
    const float4* Op4 = (const float4*)g_Op;
    float denom = 0.0f;
    float4 acc = make_float4(0.0f, 0.0f, 0.0f, 0.0f);
    #pragma unroll
    for (int s = 0; s < SP; s++) {
        if (ls[s] > 0.0f) {
            float wv = fexp2(ms[s] - m);
            denom = fmaf(wv, ls[s], denom);
            float4 o = Op4[(size_t)s * total + idx];
            acc.x = fmaf(wv, o.x, acc.x);
            acc.y = fmaf(wv, o.y, acc.y);
            acc.z = fmaf(wv, o.z, acc.z);
            acc.w = fmaf(wv, o.w, acc.w);
        }
    }
    float inv = 1.0f / denom;
    ((float4*)O)[idx] = make_float4(acc.x * inv, acc.y * inv, acc.z * inv, acc.w * inv);
}

extern "C" void kernel_launch(void* const* d_in, const int* in_sizes, int n_in,
                              void* d_out, int out_size) {
    const float* q = (const float*)d_in[0];
    const float* k = (const float*)d_in[1];
    const float* v = (const float*)d_in[2];
    float* o = (float*)d_out;

    const int B = 2;
    const int S = in_sizes[0] / (B * D);   // 8192

    size_t smem_bytes = (size_t)SMEM_FLOATS * sizeof(float);  // 103.4 KB -> 2 CTAs/SM
    cudaFuncSetAttribute(lminf_kernel, cudaFuncAttributeMaxDynamicSharedMemorySize,
                         (int)smem_bytes);

    dim3 grid(S / TQ, B, SP);
    lminf_kernel<<<grid, NTHREADS, smem_bytes>>>(q, k, v, S);

    int total4 = B * S * (D / 4);
    combine_kernel<<<(total4 + 255) / 256, 256>>>(o, S);
}